// round 1
// baseline (speedup 1.0000x reference)
#include <cuda_runtime.h>
#include <math.h>

#define Bn 4
#define Cc 64
#define Oo 64
#define Hh 128
#define Ww 128
#define HW (Hh*Ww)

// ---------------- device scratch (no allocs allowed) ----------------
__device__ float g_xt[Bn*HW*Cc];      // x transposed to [b][h][w][c]
__device__ float g_wt[9*Cc*Oo];       // dcn_w as [tap][c][o]
__device__ float g_offx[Bn*9*HW];
__device__ float g_offy[Bn*9*HW];
__device__ float g_mask[Bn*9*HW];     // sigmoid already applied
__device__ float g_stats[2*Oo];       // per-channel sum / sumsq

// ---------------- K0: NCHW -> NHWC transpose ----------------
__global__ void k_transpose(const float* __restrict__ x) {
    __shared__ float tile[32][65];           // [hw][c], pad -> conflict free
    int b   = blockIdx.y;
    int hw0 = blockIdx.x * 32;
    int tx = threadIdx.x, ty = threadIdx.y;  // (32,8)
#pragma unroll
    for (int cc = 0; cc < 8; cc++) {
        int c = cc * 8 + ty;
        tile[tx][c] = x[(b*Cc + c)*HW + hw0 + tx];   // coalesced over hw
    }
    __syncthreads();
#pragma unroll
    for (int rr = 0; rr < 4; rr++) {
        int hw = rr * 8 + ty;
        float* dst = g_xt + (size_t)(b*HW + hw0 + hw) * Cc;
        dst[tx]      = tile[hw][tx];                 // coalesced over c
        dst[tx + 32] = tile[hw][tx + 32];
    }
}

// ---------------- K0b: dcn_w [o][c][tap] -> [tap][c][o] ----------------
__global__ void k_wt(const float* __restrict__ dcn_w) {
    int i = blockIdx.x * 256 + threadIdx.x;
    if (i < 9*Cc*Oo) {
        int o = i & 63, c = (i >> 6) & 63, k = i >> 12;
        g_wt[i] = dcn_w[(o*Cc + c)*9 + k];
    }
}

// ---------------- K1: offset conv (64 -> 27) + split + sigmoid ----------------
__global__ void __launch_bounds__(256) k_offset(const float* __restrict__ ow,
                                                const float* __restrict__ ob) {
    __shared__ float wsm[27*64];                 // per-tap weights [j][c]
    int t = threadIdx.x;
    int b = blockIdx.y;
    int h = blockIdx.x * 2 + (t >> 7);           // two rows per block
    int w = t & 127;

    float acc[27];
#pragma unroll
    for (int j = 0; j < 27; j++) acc[j] = __ldg(&ob[j]);

    for (int tap = 0; tap < 9; tap++) {
        int ky = tap / 3, kx = tap % 3;
        __syncthreads();
        for (int i = t; i < 27*64; i += 256) {   // stage tap weight slab
            int c = i & 63, j = i >> 6;
            wsm[i] = ow[((j*Cc + c)*3 + ky)*3 + kx];
        }
        __syncthreads();
        int y = h + ky - 1, xq = w + kx - 1;
        if ((unsigned)y < Hh && (unsigned)xq < Ww) {
            const float4* xp = (const float4*)(g_xt + (size_t)((b*Hh + y)*Ww + xq) * Cc);
            const float4* wp = (const float4*)wsm;
#pragma unroll 4
            for (int c4 = 0; c4 < 16; c4++) {
                float4 xv = xp[c4];
#pragma unroll
                for (int j = 0; j < 27; j++) {
                    float4 wv = wp[j*16 + c4];   // broadcast across warp
                    acc[j] += xv.x*wv.x + xv.y*wv.y + xv.z*wv.z + xv.w*wv.w;
                }
            }
        }
    }
    // reference split order: off_x = om[0:9], off_y = om[9:18], mask = om[18:27]
    int base = (b*9)*HW + h*Ww + w;
#pragma unroll
    for (int k = 0; k < 9; k++) {
        int idx = base + k*HW;
        g_offx[idx] = acc[k];
        g_offy[idx] = acc[9 + k];
        g_mask[idx] = 1.f / (1.f + expf(-acc[18 + k]));
    }
}

// ---------------- K2: deformable sampling + per-tap 64x64 GEMM ----------------
// block = one (b,h) row of 128 pixels; 256 threads
// smem: ws[64*64] + samp[64*133]  (pad 133 -> conflict-free: 133 mod 32 = 5)
__global__ void __launch_bounds__(256) k_dcn(const float* __restrict__ dcn_b,
                                             float* __restrict__ out) {
    extern __shared__ float sm[];
    float* ws   = sm;            // [c][o]
    float* samp = sm + 4096;     // [c][p] stride 133

    int t    = threadIdx.x;
    int bb   = blockIdx.y, h = blockIdx.x;
    int lane = t & 31,  wrp = t >> 5;
    int oh   = t >> 7,  p   = t & 127;

    float acc[32];
#pragma unroll
    for (int i = 0; i < 32; i++) acc[i] = 0.f;

    for (int tap = 0; tap < 9; tap++) {
        int ky = tap / 3, kx = tap % 3;
        __syncthreads();                          // protect smem from prev tap
        // stage this tap's weights [c][o]
        {
            const float4* srcp = (const float4*)(g_wt + tap*4096);
            float4* dstp = (float4*)ws;
            for (int i = t; i < 1024; i += 256) dstp[i] = srcp[i];
        }
        // gather: one warp per pixel, lanes = channels (coalesced 128B loads)
        for (int pp = wrp; pp < 128; pp += 8) {
            int obase = ((bb*9 + tap)*Hh + h)*Ww + pp;
            float oy = g_offy[obase], ox = g_offx[obase], m = g_mask[obase];
            float py = (float)(h - 1 + ky) + oy;
            float px = (float)(pp - 1 + kx) + ox;
            float y0f = floorf(py), x0f = floorf(px);
            float wy = py - y0f, wx = px - x0f;
            float hy0 = (y0f >=  0.f && y0f <= 127.f) ? (1.f - wy)*m : 0.f;
            float hy1 = (y0f >= -1.f && y0f <= 126.f) ? wy*m        : 0.f;
            float gx0 = (x0f >=  0.f && x0f <= 127.f) ? (1.f - wx)  : 0.f;
            float gx1 = (x0f >= -1.f && x0f <= 126.f) ? wx          : 0.f;
            int iy0 = (int)fminf(fmaxf(y0f,       0.f), 127.f);
            int iy1 = (int)fminf(fmaxf(y0f + 1.f, 0.f), 127.f);
            int ix0 = (int)fminf(fmaxf(x0f,       0.f), 127.f);
            int ix1 = (int)fminf(fmaxf(x0f + 1.f, 0.f), 127.f);
            float w00 = hy0*gx0, w01 = hy0*gx1, w10 = hy1*gx0, w11 = hy1*gx1;
            const float* b00 = g_xt + (size_t)((bb*Hh + iy0)*Ww + ix0) * Cc;
            const float* b01 = g_xt + (size_t)((bb*Hh + iy0)*Ww + ix1) * Cc;
            const float* b10 = g_xt + (size_t)((bb*Hh + iy1)*Ww + ix0) * Cc;
            const float* b11 = g_xt + (size_t)((bb*Hh + iy1)*Ww + ix1) * Cc;
            float s0 = w00*b00[lane]    + w01*b01[lane]    + w10*b10[lane]    + w11*b11[lane];
            float s1 = w00*b00[lane+32] + w01*b01[lane+32] + w10*b10[lane+32] + w11*b11[lane+32];
            samp[lane*133 + pp]        = s0;     // 133 mod 32 = 5 -> conflict free
            samp[(lane + 32)*133 + pp] = s1;
        }
        __syncthreads();
        // GEMM: warp = 32 consecutive pixels, same o-half -> ws reads broadcast
#pragma unroll 4
        for (int c = 0; c < 64; c++) {
            float s = samp[c*133 + p];
            const float4* wrow = (const float4*)(ws + c*64 + oh*32);
#pragma unroll
            for (int i = 0; i < 8; i++) {
                float4 wv = wrow[i];
                acc[i*4+0] += s*wv.x;
                acc[i*4+1] += s*wv.y;
                acc[i*4+2] += s*wv.z;
                acc[i*4+3] += s*wv.w;
            }
        }
    }
#pragma unroll
    for (int i = 0; i < 32; i++) {
        int o = oh*32 + i;
        out[(size_t)((bb*Oo + o)*Hh + h)*Ww + p] = acc[i] + __ldg(&dcn_b[o]);
    }
}

// ---------------- K3: per-channel sum / sumsq (deterministic) ----------------
__global__ void k_stats(const float* __restrict__ out) {
    __shared__ float ssum[256], ssq[256];
    int o = blockIdx.x, t = threadIdx.x;
    float s = 0.f, q = 0.f;
    for (int i = t; i < Bn*HW; i += 256) {
        int b = i >> 14, j = i & (HW - 1);
        float v = out[(size_t)(b*Oo + o)*HW + j];
        s += v; q += v*v;
    }
    ssum[t] = s; ssq[t] = q;
    __syncthreads();
    for (int st = 128; st > 0; st >>= 1) {
        if (t < st) { ssum[t] += ssum[t+st]; ssq[t] += ssq[t+st]; }
        __syncthreads();
    }
    if (t == 0) { g_stats[o] = ssum[0]; g_stats[64 + o] = ssq[0]; }
}

// ---------------- K4: BN normalize + gamma/beta + ReLU (in place) ----------------
__global__ void k_norm(float* __restrict__ out,
                       const float* __restrict__ gamma,
                       const float* __restrict__ beta) {
    int idx = blockIdx.x * 256 + threadIdx.x;
    int o = (idx >> 14) & 63;
    const float invN = 1.f / (float)(Bn*HW);
    float s = g_stats[o], q = g_stats[64 + o];
    float mu  = s * invN;
    float var = fmaf(q, invN, -mu*mu);
    float rstd = rsqrtf(var + 1e-5f);
    float v = (out[idx] - mu) * rstd * __ldg(&gamma[o]) + __ldg(&beta[o]);
    out[idx] = fmaxf(v, 0.f);
}

// ---------------- launcher ----------------
extern "C" void kernel_launch(void* const* d_in, const int* in_sizes, int n_in,
                              void* d_out, int out_size) {
    const float* x        = (const float*)d_in[0];
    const float* offset_w = (const float*)d_in[1];
    const float* offset_b = (const float*)d_in[2];
    const float* dcn_w    = (const float*)d_in[3];
    const float* dcn_b    = (const float*)d_in[4];
    const float* gamma    = (const float*)d_in[5];
    const float* beta     = (const float*)d_in[6];
    float* out = (float*)d_out;

    const int dcn_smem = (4096 + 64*133) * sizeof(float);   // 50432 B
    cudaFuncSetAttribute(k_dcn, cudaFuncAttributeMaxDynamicSharedMemorySize, dcn_smem);

    k_transpose<<<dim3(512, Bn), dim3(32, 8)>>>(x);
    k_wt<<<144, 256>>>(dcn_w);
    k_offset<<<dim3(Hh/2, Bn), 256>>>(offset_w, offset_b);
    k_dcn<<<dim3(Hh, Bn), 256, dcn_smem>>>(dcn_b, out);
    k_stats<<<Oo, 256>>>(out);
    k_norm<<<(Bn*Oo*HW)/256, 256>>>(out, gamma, beta);
}

// round 2
// speedup vs baseline: 1.0885x; 1.0885x over previous
#include <cuda_runtime.h>
#include <math.h>

#define Bn 4
#define Cc 64
#define Oo 64
#define Hh 128
#define Ww 128
#define HW (Hh*Ww)

// ---------------- device scratch (no allocs allowed) ----------------
__device__ float g_xt[Bn*HW*Cc];      // x transposed to [b][h][w][c]
__device__ float g_wt[9*Cc*Oo];       // dcn_w as [tap][c][o]
__device__ float g_offx[Bn*9*HW];
__device__ float g_offy[Bn*9*HW];
__device__ float g_mask[Bn*9*HW];     // sigmoid already applied
__device__ float g_stats[2*Oo];       // per-channel sum / sumsq

// ---------------- f32x2 packed helpers ----------------
__device__ __forceinline__ unsigned long long f2pack(float lo, float hi) {
    unsigned long long r;
    asm("mov.b64 %0, {%1, %2};" : "=l"(r)
        : "r"(__float_as_uint(lo)), "r"(__float_as_uint(hi)));
    return r;
}
__device__ __forceinline__ void f2unpack(unsigned long long v, float &lo, float &hi) {
    unsigned int a, b;
    asm("mov.b64 {%0, %1}, %2;" : "=r"(a), "=r"(b) : "l"(v));
    lo = __uint_as_float(a); hi = __uint_as_float(b);
}
__device__ __forceinline__ void ffma2(unsigned long long &d,
                                      unsigned long long a, unsigned long long b) {
    asm("fma.rn.f32x2 %0, %1, %2, %0;" : "+l"(d) : "l"(a), "l"(b));
}

// ---------------- K0: NCHW -> NHWC transpose ----------------
__global__ void k_transpose(const float* __restrict__ x) {
    __shared__ float tile[32][65];
    int b   = blockIdx.y;
    int hw0 = blockIdx.x * 32;
    int tx = threadIdx.x, ty = threadIdx.y;  // (32,8)
#pragma unroll
    for (int cc = 0; cc < 8; cc++) {
        int c = cc * 8 + ty;
        tile[tx][c] = x[(b*Cc + c)*HW + hw0 + tx];
    }
    __syncthreads();
#pragma unroll
    for (int rr = 0; rr < 4; rr++) {
        int hw = rr * 8 + ty;
        float* dst = g_xt + (size_t)(b*HW + hw0 + hw) * Cc;
        dst[tx]      = tile[hw][tx];
        dst[tx + 32] = tile[hw][tx + 32];
    }
}

// ---------------- K0b: dcn_w [o][c][tap] -> [tap][c][o] ----------------
__global__ void k_wt(const float* __restrict__ dcn_w) {
    int i = blockIdx.x * 256 + threadIdx.x;
    if (i < 9*Cc*Oo) {
        int o = i & 63, c = (i >> 6) & 63, k = i >> 12;
        g_wt[i] = dcn_w[(o*Cc + c)*9 + k];
    }
}

// ---------------- K1: offset conv (64 -> 27) + split + sigmoid ----------------
// block = one (b,h) row, 128 threads (one per pixel). FFMA2 packed accumulators.
__global__ void __launch_bounds__(128) k_offset(const float* __restrict__ ow,
                                                const float* __restrict__ ob) {
    __shared__ float wsm[64*28];                 // [c][jpair] padded 27->28
    int t = threadIdx.x;
    int b = blockIdx.y;
    int h = blockIdx.x;
    int w = t;

    unsigned long long acc[14];
#pragma unroll
    for (int j = 0; j < 13; j++) acc[j] = f2pack(__ldg(&ob[2*j]), __ldg(&ob[2*j+1]));
    acc[13] = f2pack(__ldg(&ob[26]), 0.f);

    for (int tap = 0; tap < 9; tap++) {
        int ky = tap / 3, kx = tap % 3;
        __syncthreads();
        for (int i = t; i < 64*28; i += 128) {
            int c = i / 28, jj = i - c*28;
            wsm[i] = (jj < 27) ? ow[((jj*Cc + c)*3 + ky)*3 + kx] : 0.f;
        }
        __syncthreads();
        int y = h + ky - 1, xq = w + kx - 1;
        if ((unsigned)y < Hh && (unsigned)xq < Ww) {
            const float4* xp = (const float4*)(g_xt + (size_t)((b*Hh + y)*Ww + xq) * Cc);
#pragma unroll 2
            for (int c4 = 0; c4 < 16; c4++) {
                float4 xv = xp[c4];
                float xe[4] = {xv.x, xv.y, xv.z, xv.w};
#pragma unroll
                for (int e = 0; e < 4; e++) {
                    unsigned long long sp = f2pack(xe[e], xe[e]);
                    const ulonglong2* wr =
                        (const ulonglong2*)(wsm + (c4*4 + e)*28);  // 112B rows, 16B aligned
#pragma unroll
                    for (int q = 0; q < 7; q++) {
                        ulonglong2 wv = wr[q];        // broadcast LDS.128
                        ffma2(acc[2*q],     sp, wv.x);
                        ffma2(acc[2*q + 1], sp, wv.y);
                    }
                }
            }
        }
    }
    float a[28];
#pragma unroll
    for (int j = 0; j < 14; j++) f2unpack(acc[j], a[2*j], a[2*j+1]);
    int base = (b*9)*HW + h*Ww + w;
#pragma unroll
    for (int k = 0; k < 9; k++) {
        int idx = base + k*HW;
        g_offx[idx] = a[k];
        g_offy[idx] = a[9 + k];
        g_mask[idx] = 1.f / (1.f + expf(-a[18 + k]));
    }
}

// ---------------- K2: deformable sampling + per-tap 64x64 GEMM ----------------
// block = (b, h, p-half): 64 pixels x 64 outputs; 128 threads.
// thread tile: 8 o x 4 p (p strided by 16). FFMA2 packed.
__global__ void __launch_bounds__(128) k_dcn(const float* __restrict__ dcn_b,
                                             float* __restrict__ out) {
    __shared__ float ws[64*64];      // [c][o]
    __shared__ float samp[64*65];    // [c][p] stride 65 (conflict-free stores)

    int t    = threadIdx.x;
    int bb   = blockIdx.y, h = blockIdx.x, ph = blockIdx.z;
    int lane = t & 31,  wrp = t >> 5;
    int og   = t >> 4,  ps  = t & 15;      // warp-halves share og -> 16B dedup

    unsigned long long acc[16];            // [k(4p)][j(4 o-pairs)]
#pragma unroll
    for (int i = 0; i < 16; i++) acc[i] = 0ULL;

    for (int tap = 0; tap < 9; tap++) {
        int ky = tap / 3, kx = tap % 3;
        __syncthreads();                   // protect smem from prev-tap GEMM
        // stage this tap's weights [c][o]
        {
            const float4* srcp = (const float4*)(g_wt + tap*4096);
            float4* dstp = (float4*)ws;
#pragma unroll
            for (int i = 0; i < 8; i++) dstp[t + 128*i] = srcp[t + 128*i];
        }
        // gather 64 pixels: warp per pixel, lanes = channels (coalesced 128B LDG)
        for (int pp = wrp; pp < 64; pp += 4) {
            int wq = ph*64 + pp;
            int obase = ((bb*9 + tap)*Hh + h)*Ww + wq;
            float oy = __ldg(&g_offy[obase]), ox = __ldg(&g_offx[obase]);
            float m  = __ldg(&g_mask[obase]);
            float py = (float)(h - 1 + ky) + oy;
            float px = (float)(wq - 1 + kx) + ox;
            float y0f = floorf(py), x0f = floorf(px);
            float wy = py - y0f, wx = px - x0f;
            float hy0 = (y0f >=  0.f && y0f <= 127.f) ? (1.f - wy)*m : 0.f;
            float hy1 = (y0f >= -1.f && y0f <= 126.f) ? wy*m        : 0.f;
            float gx0 = (x0f >=  0.f && x0f <= 127.f) ? (1.f - wx)  : 0.f;
            float gx1 = (x0f >= -1.f && x0f <= 126.f) ? wx          : 0.f;
            int iy0 = (int)fminf(fmaxf(y0f,       0.f), 127.f);
            int iy1 = (int)fminf(fmaxf(y0f + 1.f, 0.f), 127.f);
            int ix0 = (int)fminf(fmaxf(x0f,       0.f), 127.f);
            int ix1 = (int)fminf(fmaxf(x0f + 1.f, 0.f), 127.f);
            float w00 = hy0*gx0, w01 = hy0*gx1, w10 = hy1*gx0, w11 = hy1*gx1;
            const float* b00 = g_xt + (size_t)((bb*Hh + iy0)*Ww + ix0) * Cc;
            const float* b01 = g_xt + (size_t)((bb*Hh + iy0)*Ww + ix1) * Cc;
            const float* b10 = g_xt + (size_t)((bb*Hh + iy1)*Ww + ix0) * Cc;
            const float* b11 = g_xt + (size_t)((bb*Hh + iy1)*Ww + ix1) * Cc;
            float s0 = w00*b00[lane]    + w01*b01[lane]    + w10*b10[lane]    + w11*b11[lane];
            float s1 = w00*b00[lane+32] + w01*b01[lane+32] + w10*b10[lane+32] + w11*b11[lane+32];
            samp[lane*65 + pp]        = s0;
            samp[(lane + 32)*65 + pp] = s1;
        }
        __syncthreads();
        // GEMM: per c: 4 scalar LDS (conflict-free) + 2 LDS.128 (dedup) + 16 FFMA2
#pragma unroll 2
        for (int c = 0; c < 64; c++) {
            const float* srow = samp + c*65 + ps;
            float s0 = srow[0], s1 = srow[16], s2 = srow[32], s3 = srow[48];
            unsigned long long p0 = f2pack(s0, s0), p1 = f2pack(s1, s1);
            unsigned long long p2 = f2pack(s2, s2), p3 = f2pack(s3, s3);
            const ulonglong2* wr = (const ulonglong2*)(ws + c*64 + og*8);
            ulonglong2 wa = wr[0], wb = wr[1];   // o pairs: (0,1)(2,3)(4,5)(6,7)
            ffma2(acc[0],  p0, wa.x); ffma2(acc[1],  p0, wa.y);
            ffma2(acc[2],  p0, wb.x); ffma2(acc[3],  p0, wb.y);
            ffma2(acc[4],  p1, wa.x); ffma2(acc[5],  p1, wa.y);
            ffma2(acc[6],  p1, wb.x); ffma2(acc[7],  p1, wb.y);
            ffma2(acc[8],  p2, wa.x); ffma2(acc[9],  p2, wa.y);
            ffma2(acc[10], p2, wb.x); ffma2(acc[11], p2, wb.y);
            ffma2(acc[12], p3, wa.x); ffma2(acc[13], p3, wa.y);
            ffma2(acc[14], p3, wb.x); ffma2(acc[15], p3, wb.y);
        }
    }
#pragma unroll
    for (int k = 0; k < 4; k++) {
        int p = ph*64 + ps + 16*k;
#pragma unroll
        for (int j = 0; j < 4; j++) {
            float lo, hi; f2unpack(acc[k*4 + j], lo, hi);
            int o = og*8 + 2*j;
            out[(size_t)(bb*Oo + o    )*HW + h*Ww + p] = lo + __ldg(&dcn_b[o]);
            out[(size_t)(bb*Oo + o + 1)*HW + h*Ww + p] = hi + __ldg(&dcn_b[o+1]);
        }
    }
}

// ---------------- K3: per-channel sum / sumsq (deterministic) ----------------
__global__ void k_stats(const float* __restrict__ out) {
    __shared__ float ssum[512], ssq[512];
    int o = blockIdx.x, t = threadIdx.x;
    float s = 0.f, q = 0.f;
    for (int i = t; i < Bn*HW; i += 512) {
        int b = i >> 14, j = i & (HW - 1);
        float v = out[(size_t)(b*Oo + o)*HW + j];
        s += v; q += v*v;
    }
    ssum[t] = s; ssq[t] = q;
    __syncthreads();
    for (int st = 256; st > 0; st >>= 1) {
        if (t < st) { ssum[t] += ssum[t+st]; ssq[t] += ssq[t+st]; }
        __syncthreads();
    }
    if (t == 0) { g_stats[o] = ssum[0]; g_stats[64 + o] = ssq[0]; }
}

// ---------------- K4: BN normalize + gamma/beta + ReLU (in place) ----------------
__global__ void k_norm(float* __restrict__ out,
                       const float* __restrict__ gamma,
                       const float* __restrict__ beta) {
    int i4 = blockIdx.x * 256 + threadIdx.x;
    int idx = i4 * 4;
    int o = (idx >> 14) & 63;
    const float invN = 1.f / (float)(Bn*HW);
    float s = g_stats[o], q = g_stats[64 + o];
    float mu  = s * invN;
    float var = fmaf(q, invN, -mu*mu);
    float rstd = rsqrtf(var + 1e-5f) * __ldg(&gamma[o]);
    float bt = __ldg(&beta[o]);
    float4 v = *(float4*)(out + idx);
    v.x = fmaxf((v.x - mu)*rstd + bt, 0.f);
    v.y = fmaxf((v.y - mu)*rstd + bt, 0.f);
    v.z = fmaxf((v.z - mu)*rstd + bt, 0.f);
    v.w = fmaxf((v.w - mu)*rstd + bt, 0.f);
    *(float4*)(out + idx) = v;
}

// ---------------- launcher ----------------
extern "C" void kernel_launch(void* const* d_in, const int* in_sizes, int n_in,
                              void* d_out, int out_size) {
    const float* x        = (const float*)d_in[0];
    const float* offset_w = (const float*)d_in[1];
    const float* offset_b = (const float*)d_in[2];
    const float* dcn_w    = (const float*)d_in[3];
    const float* dcn_b    = (const float*)d_in[4];
    const float* gamma    = (const float*)d_in[5];
    const float* beta     = (const float*)d_in[6];
    float* out = (float*)d_out;

    k_transpose<<<dim3(512, Bn), dim3(32, 8)>>>(x);
    k_wt<<<144, 256>>>(dcn_w);
    k_offset<<<dim3(Hh, Bn), 128>>>(offset_w, offset_b);
    k_dcn<<<dim3(Hh, Bn, 2), 128>>>(dcn_b, out);
    k_stats<<<Oo, 512>>>(out);
    k_norm<<<(Bn*Oo*HW)/1024, 256>>>(out, gamma, beta);
}

// round 3
// speedup vs baseline: 1.2171x; 1.1181x over previous
#include <cuda_runtime.h>
#include <math.h>

#define Bn 4
#define Cc 64
#define Oo 64
#define Hh 128
#define Ww 128
#define HW (Hh*Ww)

// ---------------- device scratch ----------------
__device__ float g_xt[Bn*HW*Cc];      // x as [b][h][w][c]
__device__ float g_wt[9*Cc*Oo];       // dcn_w as [tap][c][o]
__device__ float g_ow[9*Cc*28];       // offset_w as [tap][c][jpair-padded 28]
__device__ float g_offx[Bn*9*HW];
__device__ float g_offy[Bn*9*HW];
__device__ float g_mask[Bn*9*HW];
__device__ float g_stats[2*Oo];

// ---------------- f32x2 helpers ----------------
__device__ __forceinline__ unsigned long long f2pack(float lo, float hi) {
    unsigned long long r;
    asm("mov.b64 %0, {%1, %2};" : "=l"(r)
        : "r"(__float_as_uint(lo)), "r"(__float_as_uint(hi)));
    return r;
}
__device__ __forceinline__ void f2unpack(unsigned long long v, float &lo, float &hi) {
    unsigned int a, b;
    asm("mov.b64 {%0, %1}, %2;" : "=r"(a), "=r"(b) : "l"(v));
    lo = __uint_as_float(a); hi = __uint_as_float(b);
}
__device__ __forceinline__ void ffma2(unsigned long long &d,
                                      unsigned long long a, unsigned long long b) {
    asm("fma.rn.f32x2 %0, %1, %2, %0;" : "+l"(d) : "l"(a), "l"(b));
}

// ---------------- K0: NCHW -> NHWC ----------------
__global__ void k_transpose(const float* __restrict__ x) {
    __shared__ float tile[32][65];
    int b = blockIdx.y, hw0 = blockIdx.x * 32;
    int tx = threadIdx.x, ty = threadIdx.y;
#pragma unroll
    for (int cc = 0; cc < 8; cc++) {
        int c = cc * 8 + ty;
        tile[tx][c] = x[(b*Cc + c)*HW + hw0 + tx];
    }
    __syncthreads();
#pragma unroll
    for (int rr = 0; rr < 4; rr++) {
        int hw = rr * 8 + ty;
        float* dst = g_xt + (size_t)(b*HW + hw0 + hw) * Cc;
        dst[tx]      = tile[hw][tx];
        dst[tx + 32] = tile[hw][tx + 32];
    }
}

// ---------------- K0b: weight re-layouts ----------------
__global__ void k_wt(const float* __restrict__ dcn_w) {
    int i = blockIdx.x * 256 + threadIdx.x;
    if (i < 9*Cc*Oo) {
        int o = i & 63, c = (i >> 6) & 63, k = i >> 12;
        g_wt[i] = dcn_w[(o*Cc + c)*9 + k];
    }
}
__global__ void k_owt(const float* __restrict__ ow) {
    int i = blockIdx.x * 256 + threadIdx.x;
    if (i < 9*Cc*28) {
        int jj = i % 28, c = (i / 28) & 63, tap = i / (28*64);
        int ky = tap / 3, kx = tap % 3;
        g_ow[i] = (jj < 27) ? ow[((jj*Cc + c)*3 + ky)*3 + kx] : 0.f;
    }
}

// ---------------- K1: offset conv, 2-way channel split ----------------
// block = (b,h): 256 threads = 2 c-halves x 128 px
__global__ void __launch_bounds__(256) k_offset(const float* __restrict__ ob) {
    __shared__ float wsm[64*28];
    __shared__ float red[128*28];
    int t = threadIdx.x;
    int b = blockIdx.y, h = blockIdx.x;
    int half = t >> 7, w = t & 127;

    unsigned long long acc[14];
    if (half == 0) {
#pragma unroll
        for (int j = 0; j < 13; j++) acc[j] = f2pack(__ldg(&ob[2*j]), __ldg(&ob[2*j+1]));
        acc[13] = f2pack(__ldg(&ob[26]), 0.f);
    } else {
#pragma unroll
        for (int j = 0; j < 14; j++) acc[j] = 0ULL;
    }

    for (int tap = 0; tap < 9; tap++) {
        int ky = tap / 3, kx = tap % 3;
        __syncthreads();
        {   // coalesced stage of pre-transposed weights [c][28]
            const float4* src = (const float4*)(g_ow + tap*64*28);
            float4* dst = (float4*)wsm;
            for (int i = t; i < 448; i += 256) dst[i] = src[i];
        }
        __syncthreads();
        int y = h + ky - 1, xq = w + kx - 1;
        if ((unsigned)y < Hh && (unsigned)xq < Ww) {
            const float4* xp = (const float4*)(g_xt +
                (size_t)((b*Hh + y)*Ww + xq) * Cc + half*32);
#pragma unroll 2
            for (int c4 = 0; c4 < 8; c4++) {
                float4 xv = xp[c4];
                float xe[4] = {xv.x, xv.y, xv.z, xv.w};
#pragma unroll
                for (int e = 0; e < 4; e++) {
                    unsigned long long sp = f2pack(xe[e], xe[e]);
                    const ulonglong2* wr =
                        (const ulonglong2*)(wsm + (half*32 + c4*4 + e)*28);
#pragma unroll
                    for (int q = 0; q < 7; q++) {
                        ulonglong2 wv = wr[q];
                        ffma2(acc[2*q],     sp, wv.x);
                        ffma2(acc[2*q + 1], sp, wv.y);
                    }
                }
            }
        }
    }
    __syncthreads();
    if (half == 1) {
        float a[28];
#pragma unroll
        for (int j = 0; j < 14; j++) f2unpack(acc[j], a[2*j], a[2*j+1]);
#pragma unroll
        for (int j = 0; j < 28; j++) red[w*28 + j] = a[j];
    }
    __syncthreads();
    if (half == 0) {
        float a[28];
#pragma unroll
        for (int j = 0; j < 14; j++) {
            float lo, hi; f2unpack(acc[j], lo, hi);
            a[2*j] = lo + red[w*28 + 2*j];
            a[2*j+1] = hi + red[w*28 + 2*j+1];
        }
        int base = (b*9)*HW + h*Ww + w;
#pragma unroll
        for (int k = 0; k < 9; k++) {
            int idx = base + k*HW;
            g_offx[idx] = a[k];
            g_offy[idx] = a[9 + k];
            g_mask[idx] = 1.f / (1.f + expf(-a[18 + k]));
        }
    }
}

// ---------------- K2: DCN sampling + GEMM ----------------
// block = (b, h, px-quarter): 32 px x 64 o; 128 threads; 8 blocks/SM
__global__ void __launch_bounds__(128, 8) k_dcn(const float* __restrict__ dcn_b,
                                                float* __restrict__ out) {
    __shared__ float ws[64*64];      // [c][o]  16 KB
    __shared__ float samp[64*33];    // [c][p] stride 33, conflict-free both ways

    int t    = threadIdx.x;
    int bb   = blockIdx.y, h = blockIdx.x, pq = blockIdx.z;
    int lane = t & 31,  wrp = t >> 5;
    int og   = t >> 4,  ps  = t & 15;

    unsigned long long acc[8];       // [pxk 2][opair 4]
#pragma unroll
    for (int i = 0; i < 8; i++) acc[i] = 0ULL;

    for (int tap = 0; tap < 9; tap++) {
        int ky = tap / 3, kx = tap % 3;
        __syncthreads();
        {   // stage tap weights
            const float4* src = (const float4*)(g_wt + tap*4096);
            float4* dst = (float4*)ws;
#pragma unroll
            for (int i = 0; i < 8; i++) dst[t + 128*i] = src[t + 128*i];
        }
        // gather: warp = 8 consecutive pixels, 2-px batches for MLP
#pragma unroll
        for (int i = 0; i < 8; i += 2) {
            int pp0 = wrp*8 + i, pp1 = pp0 + 1;
            int wq0 = pq*32 + pp0, wq1 = wq0 + 1;
            int ob0 = ((bb*9 + tap)*Hh + h)*Ww + wq0;
            int ob1 = ob0 + 1;
            float oy0 = __ldg(&g_offy[ob0]), ox0 = __ldg(&g_offx[ob0]), m0 = __ldg(&g_mask[ob0]);
            float oy1 = __ldg(&g_offy[ob1]), ox1 = __ldg(&g_offx[ob1]), m1 = __ldg(&g_mask[ob1]);

            float py0 = (float)(h - 1 + ky) + oy0, px0 = (float)(wq0 - 1 + kx) + ox0;
            float py1 = (float)(h - 1 + ky) + oy1, px1 = (float)(wq1 - 1 + kx) + ox1;
            float y0f0 = floorf(py0), x0f0 = floorf(px0);
            float y0f1 = floorf(py1), x0f1 = floorf(px1);
            float wy0 = py0 - y0f0, wx0 = px0 - x0f0;
            float wy1 = py1 - y0f1, wx1 = px1 - x0f1;
            float hy00 = (y0f0 >=  0.f && y0f0 <= 127.f) ? (1.f - wy0)*m0 : 0.f;
            float hy10 = (y0f0 >= -1.f && y0f0 <= 126.f) ? wy0*m0        : 0.f;
            float gx00 = (x0f0 >=  0.f && x0f0 <= 127.f) ? (1.f - wx0)   : 0.f;
            float gx10 = (x0f0 >= -1.f && x0f0 <= 126.f) ? wx0           : 0.f;
            float hy01 = (y0f1 >=  0.f && y0f1 <= 127.f) ? (1.f - wy1)*m1 : 0.f;
            float hy11 = (y0f1 >= -1.f && y0f1 <= 126.f) ? wy1*m1        : 0.f;
            float gx01 = (x0f1 >=  0.f && x0f1 <= 127.f) ? (1.f - wx1)   : 0.f;
            float gx11 = (x0f1 >= -1.f && x0f1 <= 126.f) ? wx1           : 0.f;
            int iy00 = (int)fminf(fmaxf(y0f0,      0.f), 127.f);
            int iy10 = (int)fminf(fmaxf(y0f0 + 1.f,0.f), 127.f);
            int ix00 = (int)fminf(fmaxf(x0f0,      0.f), 127.f);
            int ix10 = (int)fminf(fmaxf(x0f0 + 1.f,0.f), 127.f);
            int iy01 = (int)fminf(fmaxf(y0f1,      0.f), 127.f);
            int iy11 = (int)fminf(fmaxf(y0f1 + 1.f,0.f), 127.f);
            int ix01 = (int)fminf(fmaxf(x0f1,      0.f), 127.f);
            int ix11 = (int)fminf(fmaxf(x0f1 + 1.f,0.f), 127.f);
            float wA0 = hy00*gx00, wB0 = hy00*gx10, wC0 = hy10*gx00, wD0 = hy10*gx10;
            float wA1 = hy01*gx01, wB1 = hy01*gx11, wC1 = hy11*gx01, wD1 = hy11*gx11;
            const float* A0 = g_xt + (size_t)((bb*Hh + iy00)*Ww + ix00) * Cc;
            const float* B0 = g_xt + (size_t)((bb*Hh + iy00)*Ww + ix10) * Cc;
            const float* C0 = g_xt + (size_t)((bb*Hh + iy10)*Ww + ix00) * Cc;
            const float* D0 = g_xt + (size_t)((bb*Hh + iy10)*Ww + ix10) * Cc;
            const float* A1 = g_xt + (size_t)((bb*Hh + iy01)*Ww + ix01) * Cc;
            const float* B1 = g_xt + (size_t)((bb*Hh + iy01)*Ww + ix11) * Cc;
            const float* C1 = g_xt + (size_t)((bb*Hh + iy11)*Ww + ix01) * Cc;
            const float* D1 = g_xt + (size_t)((bb*Hh + iy11)*Ww + ix11) * Cc;
            // 16 independent loads (ptxas front-batches these)
            float a0 = A0[lane],    b0 = B0[lane],    c0 = C0[lane],    d0 = D0[lane];
            float e0 = A0[lane+32], f0 = B0[lane+32], g0 = C0[lane+32], q0 = D0[lane+32];
            float a1 = A1[lane],    b1 = B1[lane],    c1 = C1[lane],    d1 = D1[lane];
            float e1 = A1[lane+32], f1 = B1[lane+32], g1 = C1[lane+32], q1 = D1[lane+32];
            samp[lane*33 + pp0]      = wA0*a0 + wB0*b0 + wC0*c0 + wD0*d0;
            samp[(lane+32)*33 + pp0] = wA0*e0 + wB0*f0 + wC0*g0 + wD0*q0;
            samp[lane*33 + pp1]      = wA1*a1 + wB1*b1 + wC1*c1 + wD1*d1;
            samp[(lane+32)*33 + pp1] = wA1*e1 + wB1*f1 + wC1*g1 + wD1*q1;
        }
        __syncthreads();
        // GEMM: per c: 2 LDS + 2 pack + 2 LDS.128 + 8 FFMA2
#pragma unroll 4
        for (int c = 0; c < 64; c++) {
            const float* srow = samp + c*33;
            float s0 = srow[ps], s1 = srow[ps + 16];
            unsigned long long p0 = f2pack(s0, s0), p1 = f2pack(s1, s1);
            const ulonglong2* wr = (const ulonglong2*)(ws + c*64 + og*8);
            ulonglong2 wa = wr[0], wb = wr[1];
            ffma2(acc[0], p0, wa.x); ffma2(acc[1], p0, wa.y);
            ffma2(acc[2], p0, wb.x); ffma2(acc[3], p0, wb.y);
            ffma2(acc[4], p1, wa.x); ffma2(acc[5], p1, wa.y);
            ffma2(acc[6], p1, wb.x); ffma2(acc[7], p1, wb.y);
        }
    }
#pragma unroll
    for (int k = 0; k < 2; k++) {
        int p = pq*32 + ps + 16*k;
#pragma unroll
        for (int j = 0; j < 4; j++) {
            float lo, hi; f2unpack(acc[k*4 + j], lo, hi);
            int o = og*8 + 2*j;
            out[(size_t)(bb*Oo + o    )*HW + h*Ww + p] = lo + __ldg(&dcn_b[o]);
            out[(size_t)(bb*Oo + o + 1)*HW + h*Ww + p] = hi + __ldg(&dcn_b[o+1]);
        }
    }
}

// ---------------- K3: per-channel stats ----------------
__global__ void k_stats(const float* __restrict__ out) {
    __shared__ float ssum[512], ssq[512];
    int o = blockIdx.x, t = threadIdx.x;
    float s = 0.f, q = 0.f;
    for (int i = t; i < Bn*HW; i += 512) {
        int b = i >> 14, j = i & (HW - 1);
        float v = out[(size_t)(b*Oo + o)*HW + j];
        s += v; q += v*v;
    }
    ssum[t] = s; ssq[t] = q;
    __syncthreads();
    for (int st = 256; st > 0; st >>= 1) {
        if (t < st) { ssum[t] += ssum[t+st]; ssq[t] += ssq[t+st]; }
        __syncthreads();
    }
    if (t == 0) { g_stats[o] = ssum[0]; g_stats[64 + o] = ssq[0]; }
}

// ---------------- K4: BN + ReLU ----------------
__global__ void k_norm(float* __restrict__ out,
                       const float* __restrict__ gamma,
                       const float* __restrict__ beta) {
    int i4 = blockIdx.x * 256 + threadIdx.x;
    int idx = i4 * 4;
    int o = (idx >> 14) & 63;
    const float invN = 1.f / (float)(Bn*HW);
    float s = g_stats[o], q = g_stats[64 + o];
    float mu  = s * invN;
    float var = fmaf(q, invN, -mu*mu);
    float rstd = rsqrtf(var + 1e-5f) * __ldg(&gamma[o]);
    float bt = __ldg(&beta[o]);
    float4 v = *(float4*)(out + idx);
    v.x = fmaxf((v.x - mu)*rstd + bt, 0.f);
    v.y = fmaxf((v.y - mu)*rstd + bt, 0.f);
    v.z = fmaxf((v.z - mu)*rstd + bt, 0.f);
    v.w = fmaxf((v.w - mu)*rstd + bt, 0.f);
    *(float4*)(out + idx) = v;
}

// ---------------- launcher ----------------
extern "C" void kernel_launch(void* const* d_in, const int* in_sizes, int n_in,
                              void* d_out, int out_size) {
    const float* x        = (const float*)d_in[0];
    const float* offset_w = (const float*)d_in[1];
    const float* offset_b = (const float*)d_in[2];
    const float* dcn_w    = (const float*)d_in[3];
    const float* dcn_b    = (const float*)d_in[4];
    const float* gamma    = (const float*)d_in[5];
    const float* beta     = (const float*)d_in[6];
    float* out = (float*)d_out;

    k_transpose<<<dim3(512, Bn), dim3(32, 8)>>>(x);
    k_wt<<<144, 256>>>(dcn_w);
    k_owt<<<(9*Cc*28 + 255)/256, 256>>>(offset_w);
    k_offset<<<dim3(Hh, Bn), 256>>>(offset_b);
    k_dcn<<<dim3(Hh, Bn, 4), 128>>>(dcn_b, out);
    k_stats<<<Oo, 512>>>(out);
    k_norm<<<(Bn*Oo*HW)/1024, 256>>>(out, gamma, beta);
}